// round 16
// baseline (speedup 1.0000x reference)
#include <cuda_runtime.h>
#include <cstdint>

#define R_BINS 64
#define Z_BINS 64
#define NBINS  (R_BINS * Z_BINS)
#define HSTRIDE 65                        // pad: bank = (bi + bj) % 32
#define CTAS_PER_SM 4
#define GRID_CTAS (148 * CTAS_PER_SM)     // 592
#define NTHREADS 256
#define TILE_PTS 512                      // points per tile
#define TILE_POS_BYTES (TILE_PTS * 12)    // 6144
#define TILE_MASS_BYTES (TILE_PTS * 4)    // 2048
#define TILE_BYTES (TILE_POS_BYTES + TILE_MASS_BYTES)  // 8192

#define PI_F     3.14159265358979f
#define INV_DR   6.4f
#define DR_F     0.15625f
#define DZ_F     0.0625f

// dynamic smem layout (bytes):
#define SM_HIST0  0                                   // 2 * 64*65*4 = 33280
#define SM_POS    (2 * R_BINS * HSTRIDE * 4)          // 33280
#define SM_MASS   (SM_POS + 2 * TILE_POS_BYTES)       // + 12288 = 45568
#define SM_MBAR   (SM_MASS + 2 * TILE_MASS_BYTES)     // + 4096  = 49664
#define SM_TOTAL  (SM_MBAR + 16)                      // 49680

__device__ unsigned int g_c1 = 0;         // zeroing-done arrivals (reaches 16)
__device__ unsigned int g_c2 = 0;         // flush-done arrivals (reaches grid)

__device__ __forceinline__ uint32_t smem_u32(const void* p) {
    uint32_t a;
    asm("{ .reg .u64 t; cvta.to.shared.u64 t, %1; cvt.u32.u64 %0, t; }"
        : "=r"(a) : "l"(p));
    return a;
}
__device__ __forceinline__ void mbar_init(uint32_t a, uint32_t cnt) {
    asm volatile("mbarrier.init.shared.b64 [%0], %1;" :: "r"(a), "r"(cnt) : "memory");
}
__device__ __forceinline__ void mbar_expect_tx(uint32_t a, uint32_t bytes) {
    asm volatile("mbarrier.arrive.expect_tx.shared.b64 _, [%0], %1;"
                 :: "r"(a), "r"(bytes) : "memory");
}
__device__ __forceinline__ void bulk_g2s(uint32_t dst, const void* src,
                                         uint32_t bytes, uint32_t mbar) {
    asm volatile("cp.async.bulk.shared::cta.global.mbarrier::complete_tx::bytes "
                 "[%0], [%1], %2, [%3];"
                 :: "r"(dst), "l"(src), "r"(bytes), "r"(mbar) : "memory");
}
__device__ __forceinline__ void mbar_wait(uint32_t a, uint32_t parity) {
    asm volatile(
        "{\n\t.reg .pred P;\n"
        "W%=:\n\t"
        "mbarrier.try_wait.parity.acquire.cta.shared::cta.b64 P, [%0], %1, 0x989680;\n\t"
        "@P bra D%=;\n\t"
        "bra W%=;\n"
        "D%=:\n\t}"
        :: "r"(a), "r"(parity) : "memory");
}

__device__ __forceinline__ void accum_point(float x, float y, float z, float m,
                                            float* __restrict__ h) {
    float r  = sqrtf(fmaf(x, x, y * y));
    int   bi = (int)(r * INV_DR);
    float fj = floorf((z + 2.0f) * 16.0f);
    int   bj = (int)fj;
    if (bi < R_BINS && (unsigned)bj < Z_BINS) {
        atomicAdd(&h[bi * HSTRIDE + bj], m);
    }
}

__global__ void __launch_bounds__(NTHREADS, CTAS_PER_SM)
fused_hist_kernel(const float* __restrict__ pos,    // (N,3) f32 flat
                  const float* __restrict__ mass,   // (N,)  f32
                  float* __restrict__ out,
                  int n)
{
    extern __shared__ char smem[];
    float* hists = (float*)(smem + SM_HIST0);                 // [2][R_BINS*HSTRIDE]
    const int tid = threadIdx.x;
    const int wid = tid >> 5;

    // ---- Phase 0: CTAs 0..15 zero d_out (re-zeroed every graph replay)
    if (blockIdx.x < 16) {
        out[blockIdx.x * NTHREADS + tid] = 0.0f;
        __threadfence();
        __syncthreads();
        if (tid == 0) atomicAdd(&g_c1, 1u);
    }

    // ---- init histograms + mbarriers
    for (int i = tid; i < 2 * R_BINS * HSTRIDE; i += NTHREADS)
        hists[i] = 0.0f;
    uint32_t mbar0 = smem_u32(smem + SM_MBAR);
    uint32_t mbar1 = mbar0 + 8;
    if (tid == 0) { mbar_init(mbar0, 1); mbar_init(mbar1, 1); }
    __syncthreads();

    float* hist = hists + (wid & 1) * (R_BINS * HSTRIDE);

    // ---- TMA double-buffered tile pipeline
    const int ntiles = n / TILE_PTS;                 // N=2^24 -> exact
    uint32_t pos_s[2], mass_s[2], mb[2];
    pos_s[0]  = smem_u32(smem + SM_POS);
    pos_s[1]  = pos_s[0] + TILE_POS_BYTES;
    mass_s[0] = smem_u32(smem + SM_MASS);
    mass_s[1] = mass_s[0] + TILE_MASS_BYTES;
    mb[0] = mbar0; mb[1] = mbar1;

    int t = blockIdx.x;                              // 592 CTAs, >=55 tiles each
    if (tid == 0 && t < ntiles) {
        mbar_expect_tx(mb[0], TILE_BYTES);
        bulk_g2s(pos_s[0],  pos  + (size_t)t * TILE_PTS * 3, TILE_POS_BYTES,  mb[0]);
        bulk_g2s(mass_s[0], mass + (size_t)t * TILE_PTS,     TILE_MASS_BYTES, mb[0]);
    }

    int buf = 0;
    int ph0 = 0, ph1 = 0;
    for (; t < ntiles; t += gridDim.x) {
        int t_next = t + gridDim.x;

        // wait for current buffer
        if (buf == 0) { mbar_wait(mb[0], ph0); ph0 ^= 1; }
        else          { mbar_wait(mb[1], ph1); ph1 ^= 1; }

        // prefetch next tile into other buffer (free since last iter's sync)
        if (tid == 0 && t_next < ntiles) {
            int nb = buf ^ 1;
            mbar_expect_tx(mb[nb], TILE_BYTES);
            bulk_g2s(pos_s[nb],  pos  + (size_t)t_next * TILE_PTS * 3, TILE_POS_BYTES,  mb[nb]);
            bulk_g2s(mass_s[nb], mass + (size_t)t_next * TILE_PTS,     TILE_MASS_BYTES, mb[nb]);
        }

        // process current tile from smem: 2 points/thread, stride-3 LDS conflict-free
        {
            const float* sp = (const float*)(smem + SM_POS)  + buf * (TILE_POS_BYTES / 4);
            const float* sm = (const float*)(smem + SM_MASS) + buf * (TILE_MASS_BYTES / 4);
            #pragma unroll
            for (int k = 0; k < TILE_PTS / NTHREADS; k++) {
                int p = tid + k * NTHREADS;
                float x = sp[3 * p + 0];
                float y = sp[3 * p + 1];
                float z = sp[3 * p + 2];
                float m = sm[p];
                accum_point(x, y, z, m, hist);
            }
        }
        __syncthreads();            // all lanes done reading buf before it refills
        buf ^= 1;
    }

    // ---- leftover points (n % TILE_PTS), CTA 0 only — none for N=2^24
    if (blockIdx.x == 0) {
        for (int p = ntiles * TILE_PTS + tid; p < n; p += NTHREADS) {
            accum_point(pos[3 * p], pos[3 * p + 1], pos[3 * p + 2], mass[p], hist);
        }
    }
    __syncthreads();

    // ---- wait until d_out is zeroed (flag set at kernel start by CTAs 0..15)
    if (tid == 0) {
        while (atomicAdd(&g_c1, 0u) < 16u) { __nanosleep(64); }
    }
    __syncthreads();
    __threadfence();

    // ---- flush, pre-scaled by 1/volume (normalize folded in)
    for (int i = tid; i < NBINS; i += NTHREADS) {
        int row = i >> 6;
        int col = i & 63;
        float v = hists[row * HSTRIDE + col] +
                  hists[R_BINS * HSTRIDE + row * HSTRIDE + col];
        if (v != 0.0f) {
            float r0  = (float)row * DR_F;
            float r1  = (float)(row + 1) * DR_F;
            float vol = PI_F * (r1 * r1 - r0 * r0) * DZ_F;
            atomicAdd(&out[i], v / vol);
        }
    }

    // ---- last CTA resets counters (deterministic across replays)
    __threadfence();
    __syncthreads();
    if (tid == 0) {
        unsigned int v = atomicAdd(&g_c2, 1u);
        if (v == gridDim.x - 1) {
            atomicExch(&g_c1, 0u);
            atomicExch(&g_c2, 0u);
        }
    }
}

extern "C" void kernel_launch(void* const* d_in, const int* in_sizes, int n_in,
                              void* d_out, int out_size) {
    const float* pos  = (const float*)d_in[0];
    const float* mass = (const float*)d_in[1];
    float* out = (float*)d_out;
    int n = in_sizes[1];     // N = 2^24

    cudaFuncSetAttribute(fused_hist_kernel,
                         cudaFuncAttributeMaxDynamicSharedMemorySize, SM_TOTAL);

    fused_hist_kernel<<<GRID_CTAS, NTHREADS, SM_TOTAL>>>(pos, mass, out, n);
}

// round 17
// speedup vs baseline: 1.2872x; 1.2872x over previous
#include <cuda_runtime.h>

#define R_BINS 64
#define Z_BINS 64
#define NBINS  (R_BINS * Z_BINS)
#define HSTRIDE 65                       // pad: bank = (bi + bj) % 32
#define CTAS_PER_SM 4
#define GRID_CTAS (148 * CTAS_PER_SM)    // 592, proven best config
#define NTHREADS 256
#define WARPS_PER_CTA (NTHREADS / 32)

#define PI_F     3.14159265358979f
#define DR_F     0.15625f
#define DZ_F     0.0625f

__device__ unsigned int g_c1 = 0;        // zeroing-done arrivals (reaches 16)
__device__ unsigned int g_c2 = 0;        // flush-done arrivals (reaches grid)

__device__ __forceinline__ void accum_point(float x, float y, float z, float m,
                                            float* __restrict__ h) {
    float r2 = fmaf(x, x, y * y);
    float r;
    asm("sqrt.approx.f32 %0, %1;" : "=f"(r) : "f"(r2));     // 1 MUFU, no fixups
    float fr = r * 6.4f;
    float fz = (z + 2.0f) * 16.0f;                          // matches ref rounding
    int bi, bj;
    asm("cvt.rmi.s32.f32 %0, %1;" : "=r"(bi) : "f"(fr));    // fused floor+cvt
    asm("cvt.rmi.s32.f32 %0, %1;" : "=r"(bj) : "f"(fz));
    if (bi < R_BINS && (unsigned)bj < Z_BINS) {
        atomicAdd(&h[bi * HSTRIDE + bj], m);
    }
}

// Unguarded load of 4 points (lane-strided by 32) from a full 128-pt block.
__device__ __forceinline__ void load_block(const float* __restrict__ pos,
                                           const float* __restrict__ mass,
                                           int blockStart, int lane,
                                           float* x, float* y, float* z, float* m) {
    const int p0 = blockStart + lane;
    const float* pp = pos + 3 * (size_t)p0;
    const float* mp = mass + p0;
    #pragma unroll
    for (int k = 0; k < 4; k++) {
        x[k] = __ldcs(pp + 96 * k + 0);   // immediate offsets, streaming
        y[k] = __ldcs(pp + 96 * k + 1);
        z[k] = __ldcs(pp + 96 * k + 2);
        m[k] = __ldcs(mp + 32 * k);
    }
}

__device__ __forceinline__ void process_batch(const float* x, const float* y,
                                              const float* z, const float* m,
                                              float* __restrict__ hist) {
    #pragma unroll
    for (int k = 0; k < 4; k++)
        accum_point(x[k], y[k], z[k], m[k], hist);
}

__global__ void __launch_bounds__(NTHREADS, CTAS_PER_SM)
fused_hist_kernel(const float* __restrict__ pos,    // (N,3) f32 flat
                  const float* __restrict__ mass,   // (N,)  f32
                  float* __restrict__ out,
                  int n)                            // N (divisible by 128)
{
    __shared__ float sh[2][R_BINS * HSTRIDE];

    const int tid  = threadIdx.x;
    const int wid  = tid >> 5;
    const int lane = tid & 31;

    // ---- Phase 0: CTAs 0..15 zero d_out (re-zeroed every graph replay)
    if (blockIdx.x < 16) {
        out[blockIdx.x * NTHREADS + tid] = 0.0f;
        __threadfence();
        __syncthreads();
        if (tid == 0) atomicAdd(&g_c1, 1u);
    }

    // ---- Phase 1: private histograms (2 sub-hists by warp parity)
    float* hist = sh[wid & 1];
    for (int i = tid; i < 2 * R_BINS * HSTRIDE; i += NTHREADS)
        (&sh[0][0])[i] = 0.0f;
    __syncthreads();

    // Warp-granular grid stride over full 128-point blocks (no guards needed:
    // n % 128 == 0). Ping-pong double buffer, depth-1 prefetch.
    const int nblocks = n >> 7;
    const int nw      = gridDim.x * WARPS_PER_CTA;
    int i = blockIdx.x * WARPS_PER_CTA + wid;

    if (i < nblocks) {
        float xa[4], ya[4], za[4], ma[4];
        float xb[4], yb[4], zb[4], mb[4];

        load_block(pos, mass, i << 7, lane, xa, ya, za, ma);   // batch A
        i += nw;

        while (i < nblocks) {
            load_block(pos, mass, i << 7, lane, xb, yb, zb, mb);   // prefetch B
            process_batch(xa, ya, za, ma, hist);                   // process A
            i += nw;
            if (i >= nblocks) {                                    // B is last
                process_batch(xb, yb, zb, mb, hist);
                goto mainloop_done;
            }
            load_block(pos, mass, i << 7, lane, xa, ya, za, ma);   // prefetch A
            process_batch(xb, yb, zb, mb, hist);                   // process B
            i += nw;
        }
        process_batch(xa, ya, za, ma, hist);                       // lone A
        mainloop_done: ;
    }

    // ---- tail points (n % 128), CTA 0 only — empty for N = 2^24
    if (blockIdx.x == 0) {
        for (int p = (nblocks << 7) + tid; p < n; p += NTHREADS)
            accum_point(pos[3 * p], pos[3 * p + 1], pos[3 * p + 2], mass[p], hist);
    }
    __syncthreads();

    // ---- Phase 2: wait until d_out is zeroed (flag set at kernel start by
    // first-wave CTAs 0..15, so no deadlock)
    if (tid == 0) {
        while (atomicAdd(&g_c1, 0u) < 16u) { __nanosleep(64); }
    }
    __syncthreads();
    __threadfence();

    // ---- Phase 3: flush, pre-scaled by 1/volume (normalize folded in)
    for (int i2 = tid; i2 < NBINS; i2 += NTHREADS) {
        int row = i2 >> 6;
        int col = i2 & 63;
        float v = sh[0][row * HSTRIDE + col] + sh[1][row * HSTRIDE + col];
        if (v != 0.0f) {
            float r0  = (float)row * DR_F;
            float r1  = (float)(row + 1) * DR_F;
            float vol = PI_F * (r1 * r1 - r0 * r0) * DZ_F;
            atomicAdd(&out[i2], v / vol);
        }
    }

    // ---- Phase 4: last CTA resets counters (deterministic across replays)
    __threadfence();
    __syncthreads();
    if (tid == 0) {
        unsigned int v = atomicAdd(&g_c2, 1u);
        if (v == gridDim.x - 1) {
            atomicExch(&g_c1, 0u);
            atomicExch(&g_c2, 0u);
        }
    }
}

extern "C" void kernel_launch(void* const* d_in, const int* in_sizes, int n_in,
                              void* d_out, int out_size) {
    const float* pos  = (const float*)d_in[0];   // positions (N,3) f32
    const float* mass = (const float*)d_in[1];   // masses (N,) f32
    float* out = (float*)d_out;

    int n = in_sizes[1];     // N = 2^24

    fused_hist_kernel<<<GRID_CTAS, NTHREADS>>>(pos, mass, out, n);
}